// round 5
// baseline (speedup 1.0000x reference)
#include <cuda_runtime.h>

#define HWPIX 4096
#define NT 216
#define EMBROW 36928     // 64*577 floats
#define EMBBYTES 147712  // EMBROW*4
#define FROW 577
#define NP 32
#define PSTRIDE 34
#define W2STRIDE 68
#define NSTG 3
#define MTHREADS 512

typedef unsigned long long ull;

__device__ __forceinline__ ull pack_dup(float v) {
    ull r;
    asm("mov.b64 %0, {%1, %1};" : "=l"(r) : "f"(v));
    return r;
}
__device__ __forceinline__ void fma2(ull& acc, ull a, ull b) {
    asm("fma.rn.f32x2 %0, %1, %2, %0;" : "+l"(acc) : "l"(a), "l"(b));
}
__device__ __forceinline__ void unpack2(float& lo, float& hi, ull v) {
    asm("mov.b64 {%0, %1}, %2;" : "=f"(lo), "=f"(hi) : "l"(v));
}
__device__ __forceinline__ unsigned smem_u32(const void* p) {
    unsigned a;
    asm("{ .reg .u64 t; cvta.to.shared.u64 t, %1; cvt.u32.u64 %0, t; }" : "=r"(a) : "l"(p));
    return a;
}

// ---------- device scratch ----------
__device__ __align__(16) float g_h[HWPIX * 64];   // h in HWC layout
__device__ int g_hist16[16][NT];
__device__ int g_count[NT];
__device__ int g_start[NT];
__device__ int g_order[NT];
__device__ int g_pix[HWPIX];

// ---------- launch 1: conv1 (blocks 0..63) + histogram (blocks 64..79) ----------
__global__ __launch_bounds__(256) void k_conv1hist(const float* __restrict__ x,
                                                   const float* __restrict__ w1,
                                                   const float* __restrict__ b1,
                                                   const int* __restrict__ buckets) {
    int blk = blockIdx.x;
    int tid = threadIdx.x;

    if (blk >= 64) {
        __shared__ int hist[NT];
        int hb = blk - 64;
        for (int i = tid; i < NT; i += 256) hist[i] = 0;
        __syncthreads();
        if (tid < 256) atomicAdd(&hist[buckets[hb * 256 + tid]], 1);
        __syncthreads();
        for (int i = tid; i < NT; i += 256) g_hist16[hb][i] = hist[i];
        return;
    }

    __shared__ float xs[16][18][18];
    __shared__ __align__(16) float wsm[144 * 20];
    int g = blk >> 4;
    int y0 = ((blk >> 2) & 3) * 16, x0 = (blk & 3) * 16;

    for (int idx = tid; idx < 2304; idx += 256) {
        int oc = idx / 144, m = idx - oc * 144;
        wsm[m * 20 + oc] = w1[(g * 16 + oc) * 144 + m];
    }
    for (int idx = tid; idx < 16 * 324; idx += 256) {
        int ci = idx / 324, r = idx - ci * 324;
        int yl = r / 18, xl = r - yl * 18;
        int yy = y0 - 1 + yl, xx = x0 - 1 + xl;
        float v = 0.f;
        if ((unsigned)yy < 64u && (unsigned)xx < 64u)
            v = x[(g * 16 + ci) * HWPIX + yy * 64 + xx];
        xs[ci][yl][xl] = v;
    }
    __syncthreads();

    int ty = tid >> 4, tx = tid & 15;
    float acc[16];
#pragma unroll
    for (int oc = 0; oc < 16; oc++) acc[oc] = __ldg(&b1[g * 16 + oc]);

    for (int ci = 0; ci < 16; ci++) {
#pragma unroll
        for (int s = 0; s < 9; s++) {
            float xv = xs[ci][ty + s / 3][tx + s % 3];
            int m = ci * 9 + s;
#pragma unroll
            for (int q = 0; q < 4; q++) {
                float4 w = *(const float4*)&wsm[m * 20 + q * 4];
                acc[q * 4 + 0] += w.x * xv;
                acc[q * 4 + 1] += w.y * xv;
                acc[q * 4 + 2] += w.z * xv;
                acc[q * 4 + 3] += w.w * xv;
            }
        }
    }
    int gy = y0 + ty, gx = x0 + tx;
    float* hp = &g_h[(gy * 64 + gx) * 64 + g * 16];
#pragma unroll
    for (int q = 0; q < 4; q++) {
        float4 r;
        r.x = fmaxf(acc[q * 4 + 0], 0.f);
        r.y = fmaxf(acc[q * 4 + 1], 0.f);
        r.z = fmaxf(acc[q * 4 + 2], 0.f);
        r.w = fmaxf(acc[q * 4 + 3], 0.f);
        *(float4*)&hp[q * 4] = r;
    }
}

// ---------- launch 2: fused scan + scatter (16 blocks; each redoes the tiny scan) ----------
__global__ __launch_bounds__(256) void k_scanscatter(const int* __restrict__ buckets) {
    __shared__ int cnt[256];
    __shared__ int scan[256];
    __shared__ int cur[NT];
    int tid = threadIdx.x;
    int j = blockIdx.x;

    int v = 0;
    if (tid < NT)
#pragma unroll
        for (int k = 0; k < 16; k++) v += g_hist16[k][tid];
    cnt[tid] = v;
    scan[tid] = v;
    __syncthreads();
    for (int off = 1; off < 256; off <<= 1) {
        int t = (tid >= off) ? scan[tid - off] : 0;
        __syncthreads();
        scan[tid] += t;
        __syncthreads();
    }
    if (tid < NT) {
        int excl = scan[tid] - v;
        int off = excl;
        for (int k = 0; k < j; k++) off += g_hist16[k][tid];
        cur[tid] = off;
        if (j == 0) {
            g_count[tid] = v;
            g_start[tid] = excl;
            int rank = 0;
            for (int q = 0; q < NT; q++) {
                int cq = cnt[q];
                rank += (cq > v) || (cq == v && q < tid);
            }
            g_order[rank] = tid;
        }
    }
    __syncthreads();
    int i = j * 256 + tid;
    int b = buckets[i];
    int pos = atomicAdd(&cur[b], 1);
    g_pix[pos] = i;
}

// ---------- launch 3: per-bucket dynamic conv GEMM, 512 threads, F via TMA ----------
__global__ __launch_bounds__(MTHREADS) void k_main(const float* __restrict__ x,
                                                   const float* __restrict__ emb,
                                                   const float* __restrict__ w2,
                                                   const float* __restrict__ b2,
                                                   float* __restrict__ out) {
    extern __shared__ float sm[];
    float* Fs = sm;                             // 64 x 577 dense (TMA target)
    float* w2s = sm + EMBROW;                   // 64 x 68
    float* patch = w2s + 64 * W2STRIDE;         // 144 x 34 (aliased as zbuf)
    __shared__ int pixels[NP];
    __shared__ __align__(8) ull mbar;

    int t = g_order[blockIdx.x];
    int tid = threadIdx.x;
    int n = g_count[t];
    int start = g_start[t];

    unsigned mb = smem_u32(&mbar);
    if (tid == 0) {
        asm volatile("mbarrier.init.shared.b64 [%0], 1;" :: "r"(mb) : "memory");
        asm volatile("fence.proxy.async.shared::cta;" ::: "memory");
        asm volatile("mbarrier.arrive.expect_tx.shared.b64 _, [%0], %1;"
                     :: "r"(mb), "r"(EMBBYTES) : "memory");
        asm volatile("cp.async.bulk.shared::cta.global.mbarrier::complete_tx::bytes "
                     "[%0], [%1], %2, [%3];"
                     :: "r"(smem_u32(Fs)), "l"(emb + (size_t)t * EMBROW),
                        "r"(EMBBYTES), "r"(mb) : "memory");
    }

    // w2 into padded smem rows
    for (int idx = tid * 4; idx < 4096; idx += MTHREADS * 4) {
        *(float4*)&w2s[(idx >> 6) * W2STRIDE + (idx & 63)] = *(const float4*)(w2 + idx);
    }

    int o = tid >> 3;     // 0..63 : this thread's output channel
    int pt = tid & 7;     // 0..7  : pixels 4pt .. 4pt+3

    // precomputed staging decomposition
    int pp[NSTG], soff[NSTG], sy[NSTG], sx[NSTG], chq[NSTG];
    bool qv_ok[NSTG];
#pragma unroll
    for (int i = 0; i < NSTG; i++) {
        int q = tid + i * MTHREADS;
        qv_ok[i] = (q < 1152);
        int qq = qv_ok[i] ? q : 0;
        int p = qq / 36;
        int r = qq - p * 36;
        int cq = r & 3, s = r >> 2;
        pp[i] = p;
        sy[i] = s / 3 - 1;
        sx[i] = s % 3 - 1;
        soff[i] = ((cq * 4) * 9 + s) * PSTRIDE + p;
        chq[i] = cq * 4;
    }

    float4 sv[NSTG];
    bool waited = false;

    for (int pb = 0; pb < n; pb += NP) {
        int npc = min(NP, n - pb);
        __syncthreads();
        if (tid < NP) pixels[tid] = g_pix[start + pb + min(tid, npc - 1)];
        __syncthreads();

        // stage slab c=0
#pragma unroll
        for (int i = 0; i < NSTG; i++) {
            if (qv_ok[i]) {
                int pix = pixels[pp[i]];
                int yy = (pix >> 6) + sy[i], xx = (pix & 63) + sx[i];
                float4 v = make_float4(0.f, 0.f, 0.f, 0.f);
                if ((unsigned)yy < 64u && (unsigned)xx < 64u)
                    v = *(const float4*)&g_h[((yy << 6) + xx) * 64 + chq[i]];
                sv[i] = v;
            }
        }

        ull acc0 = 0, acc1 = 0;   // px {0,1}, {2,3} for this thread's o

        for (int c = 0; c < 4; c++) {
#pragma unroll
            for (int i = 0; i < NSTG; i++) {
                if (qv_ok[i]) {
                    patch[soff[i] + 0 * 9 * PSTRIDE] = sv[i].x;
                    patch[soff[i] + 1 * 9 * PSTRIDE] = sv[i].y;
                    patch[soff[i] + 2 * 9 * PSTRIDE] = sv[i].z;
                    patch[soff[i] + 3 * 9 * PSTRIDE] = sv[i].w;
                }
            }
            __syncthreads();

            if (c < 3) {
                int c0n = (c + 1) * 16;
#pragma unroll
                for (int i = 0; i < NSTG; i++) {
                    if (qv_ok[i]) {
                        int pix = pixels[pp[i]];
                        int yy = (pix >> 6) + sy[i], xx = (pix & 63) + sx[i];
                        float4 v = make_float4(0.f, 0.f, 0.f, 0.f);
                        if ((unsigned)yy < 64u && (unsigned)xx < 64u)
                            v = *(const float4*)&g_h[((yy << 6) + xx) * 64 + c0n + chq[i]];
                        sv[i] = v;
                    }
                }
            }

            if (!waited) {
                unsigned done;
                do {
                    asm volatile("{\n\t.reg .pred p;\n\t"
                                 "mbarrier.try_wait.parity.acquire.cta.shared::cta.b64 p, [%1], 0, 0x989680;\n\t"
                                 "selp.b32 %0, 1, 0, p;\n\t}"
                                 : "=r"(done) : "r"(mb) : "memory");
                } while (!done);
                waited = true;
            }

            // GEMM slab: acc[px] += F[o][k] * patch[k][px]
            {
                const float* Fo = Fs + o * FROW + c * 144;
                const float* Pb = patch + pt * 4;
#pragma unroll 8
                for (int ck = 0; ck < 144; ck++) {
                    ull d = pack_dup(Fo[ck]);
                    ull p01 = *(const ull*)&Pb[ck * PSTRIDE];
                    ull p23 = *(const ull*)&Pb[ck * PSTRIDE + 2];
                    fma2(acc0, d, p01);
                    fma2(acc1, d, p23);
                }
            }
            __syncthreads();
        }

        float a[4];
        unpack2(a[0], a[1], acc0);
        unpack2(a[2], a[3], acc1);

        // dyn bias + relu -> zbuf (aliases patch)
        float* zbuf = patch;
        {
            float bs = Fs[o * FROW + 576];
#pragma unroll
            for (int j = 0; j < 4; j++)
                zbuf[o * PSTRIDE + pt * 4 + j] = fmaxf(a[j] + bs, 0.f);
        }
        __syncthreads();

        // 1x1 conv + b2
        ull b01 = pack_dup(__ldg(&b2[o]));
        ull b23 = b01;
        {
            const float* zb = zbuf + pt * 4;
            const float* wr = w2s + o * W2STRIDE;
#pragma unroll 8
            for (int z = 0; z < 64; z++) {
                ull w = pack_dup(wr[z]);
                fma2(b01, w, *(const ull*)&zb[z * PSTRIDE]);
                fma2(b23, w, *(const ull*)&zb[z * PSTRIDE + 2]);
            }
        }
        float a2[4];
        unpack2(a2[0], a2[1], b01);
        unpack2(a2[2], a2[3], b23);

        // residual + relu + store
#pragma unroll
        for (int j = 0; j < 4; j++) {
            int p = pt * 4 + j;
            if (p < npc) {
                int pix = pixels[p];
                float v = a2[j] + __ldg(&x[o * HWPIX + pix]);
                out[o * HWPIX + pix] = fmaxf(v, 0.f);
            }
        }
    }
}

extern "C" void kernel_launch(void* const* d_in, const int* in_sizes, int n_in,
                              void* d_out, int out_size) {
    const float* x   = (const float*)d_in[0];
    const int* bk    = (const int*)d_in[1];
    const float* w1  = (const float*)d_in[2];
    const float* b1  = (const float*)d_in[3];
    const float* emb = (const float*)d_in[4];
    const float* w2  = (const float*)d_in[5];
    const float* b2  = (const float*)d_in[6];
    float* out = (float*)d_out;

    k_conv1hist<<<80, 256>>>(x, w1, b1, bk);
    k_scanscatter<<<16, 256>>>(bk);

    size_t smem = (size_t)(EMBROW + 64 * W2STRIDE + 144 * PSTRIDE) * sizeof(float); // 184704 B
    cudaFuncSetAttribute(k_main, cudaFuncAttributeMaxDynamicSharedMemorySize, (int)smem);
    k_main<<<NT, MTHREADS, smem>>>(x, emb, w2, b2, out);
}

// round 6
// speedup vs baseline: 1.3241x; 1.3241x over previous
#include <cuda_runtime.h>

#define HWPIX 4096
#define NT 216
#define EMBROW 36928      // 64*577 floats per bucket
#define FROW 577
#define HALF_F 18464      // 32*577 floats
#define HALF_FB 73856     // bytes
#define NP 32
#define PSTRIDE 34
#define NSTG 5

typedef unsigned long long ull;

__device__ __forceinline__ ull pack_dup(float v) {
    ull r;
    asm("mov.b64 %0, {%1, %1};" : "=l"(r) : "f"(v));
    return r;
}
__device__ __forceinline__ void fma2(ull& acc, ull a, ull b) {
    asm("fma.rn.f32x2 %0, %1, %2, %0;" : "+l"(acc) : "l"(a), "l"(b));
}
__device__ __forceinline__ void unpack2(float& lo, float& hi, ull v) {
    asm("mov.b64 {%0, %1}, %2;" : "=f"(lo), "=f"(hi) : "l"(v));
}
__device__ __forceinline__ unsigned smem_u32(const void* p) {
    unsigned a;
    asm("{ .reg .u64 t; cvta.to.shared.u64 t, %1; cvt.u32.u64 %0, t; }" : "=r"(a) : "l"(p));
    return a;
}

// ---------- device scratch ----------
__device__ __align__(16) float g_h[HWPIX * 64];   // conv1 out, HWC
__device__ __align__(16) float g_z[HWPIX * 64];   // dyn-conv out (relu'd), HWC
__device__ int g_hist16[16][NT];
__device__ int g_count[NT];
__device__ int g_start[NT];
__device__ int g_order[NT];
__device__ int g_pix[HWPIX];

// ---------- launch 1: conv1 (256 blocks, oc-split x4) + histogram (16 blocks) ----------
__global__ __launch_bounds__(256) void k_conv1hist(const float* __restrict__ x,
                                                   const float* __restrict__ w1,
                                                   const float* __restrict__ b1,
                                                   const int* __restrict__ buckets) {
    int blk = blockIdx.x;
    int tid = threadIdx.x;

    if (blk >= 256) {
        __shared__ int hist[NT];
        int hb = blk - 256;
        for (int i = tid; i < NT; i += 256) hist[i] = 0;
        __syncthreads();
        atomicAdd(&hist[buckets[hb * 256 + tid]], 1);
        __syncthreads();
        for (int i = tid; i < NT; i += 256) g_hist16[hb][i] = hist[i];
        return;
    }

    int tile = blk >> 2;
    int ocq = blk & 3;                // 4 output channels: g*16 + ocq*4 ..
    int g = tile >> 4;
    int y0 = ((tile >> 2) & 3) * 16, x0 = (tile & 3) * 16;

    __shared__ float xs[16][18][18];
    __shared__ __align__(16) float wsm[144 * 4];

    // weights: 4 oc x 144, transposed -> wsm[m*4 + i]
    for (int idx = tid; idx < 576; idx += 256) {
        int i = idx / 144, m = idx - i * 144;
        wsm[m * 4 + i] = w1[(g * 16 + ocq * 4 + i) * 144 + m];
    }
    for (int idx = tid; idx < 16 * 324; idx += 256) {
        int ci = idx / 324, r = idx - ci * 324;
        int yl = r / 18, xl = r - yl * 18;
        int yy = y0 - 1 + yl, xx = x0 - 1 + xl;
        float v = 0.f;
        if ((unsigned)yy < 64u && (unsigned)xx < 64u)
            v = x[(g * 16 + ci) * HWPIX + yy * 64 + xx];
        xs[ci][yl][xl] = v;
    }
    __syncthreads();

    int ty = tid >> 4, tx = tid & 15;
    float acc[4];
#pragma unroll
    for (int i = 0; i < 4; i++) acc[i] = __ldg(&b1[g * 16 + ocq * 4 + i]);

    for (int ci = 0; ci < 16; ci++) {
#pragma unroll
        for (int s = 0; s < 9; s++) {
            float xv = xs[ci][ty + s / 3][tx + s % 3];
            float4 w = *(const float4*)&wsm[(ci * 9 + s) * 4];
            acc[0] += w.x * xv;
            acc[1] += w.y * xv;
            acc[2] += w.z * xv;
            acc[3] += w.w * xv;
        }
    }
    int gy = y0 + ty, gx = x0 + tx;
    float4 r;
    r.x = fmaxf(acc[0], 0.f);
    r.y = fmaxf(acc[1], 0.f);
    r.z = fmaxf(acc[2], 0.f);
    r.w = fmaxf(acc[3], 0.f);
    *(float4*)&g_h[(gy * 64 + gx) * 64 + g * 16 + ocq * 4] = r;
}

// ---------- launch 2: fused scan + scatter (16 blocks) ----------
__global__ __launch_bounds__(256) void k_scanscatter(const int* __restrict__ buckets) {
    __shared__ int cnt[256];
    __shared__ int scan[256];
    __shared__ int cur[NT];
    int tid = threadIdx.x;
    int j = blockIdx.x;

    int v = 0;
    if (tid < NT)
#pragma unroll
        for (int k = 0; k < 16; k++) v += g_hist16[k][tid];
    cnt[tid] = v;
    scan[tid] = v;
    __syncthreads();
    for (int off = 1; off < 256; off <<= 1) {
        int t = (tid >= off) ? scan[tid - off] : 0;
        __syncthreads();
        scan[tid] += t;
        __syncthreads();
    }
    if (tid < NT) {
        int excl = scan[tid] - v;
        int off = excl;
        for (int k = 0; k < j; k++) off += g_hist16[k][tid];
        cur[tid] = off;
        if (j == 0) {
            g_count[tid] = v;
            g_start[tid] = excl;
            int rank = 0;
            for (int q = 0; q < NT; q++) {
                int cq = cnt[q];
                rank += (cq > v) || (cq == v && q < tid);
            }
            g_order[rank] = tid;
        }
    }
    __syncthreads();
    int i = j * 256 + tid;
    int b = buckets[i];
    int pos = atomicAdd(&cur[b], 1);
    g_pix[pos] = i;
}

// ---------- launch 3: dynamic conv, 432 blocks (bucket x o-half), z -> global ----------
__global__ __launch_bounds__(256) void k_dyn(const float* __restrict__ emb) {
    extern __shared__ float sm[];
    float* Fs = sm;                      // 32 x 577 (TMA target)
    float* patch = sm + HALF_F;          // 144 x 34
    __shared__ int pixels[NP];
    __shared__ __align__(8) ull mbar;

    int t = g_order[blockIdx.x >> 1];
    int half = blockIdx.x & 1;
    int tid = threadIdx.x;
    int n = g_count[t];
    int start = g_start[t];
    if (n == 0) return;

    unsigned mb = smem_u32(&mbar);
    if (tid == 0) {
        asm volatile("mbarrier.init.shared.b64 [%0], 1;" :: "r"(mb) : "memory");
        asm volatile("fence.proxy.async.shared::cta;" ::: "memory");
        asm volatile("mbarrier.arrive.expect_tx.shared.b64 _, [%0], %1;"
                     :: "r"(mb), "r"(HALF_FB) : "memory");
        asm volatile("cp.async.bulk.shared::cta.global.mbarrier::complete_tx::bytes "
                     "[%0], [%1], %2, [%3];"
                     :: "r"(smem_u32(Fs)),
                        "l"(emb + (size_t)t * EMBROW + half * HALF_F),
                        "r"(HALF_FB), "r"(mb) : "memory");
    }

    int o = tid & 31;        // lane: o within half (F rows conflict-free: 577 % 32 == 1)
    int pxg = tid >> 5;      // 0..7 : pixels 4pxg .. 4pxg+3

    // staging decomposition (loop-invariant)
    int pp[NSTG], soff[NSTG], sy[NSTG], sx[NSTG], chq[NSTG];
    bool qv_ok[NSTG];
#pragma unroll
    for (int i = 0; i < NSTG; i++) {
        int q = tid + i * 256;
        qv_ok[i] = (q < 1152);
        int qq = qv_ok[i] ? q : 0;
        int p = qq / 36;
        int r = qq - p * 36;
        int cq = r & 3, s = r >> 2;
        pp[i] = p;
        sy[i] = s / 3 - 1;
        sx[i] = s % 3 - 1;
        soff[i] = ((cq * 4) * 9 + s) * PSTRIDE + p;
        chq[i] = cq * 4;
    }

    float4 sv[NSTG];
    bool waited = false;

    for (int pb = 0; pb < n; pb += NP) {
        int npc = min(NP, n - pb);
        __syncthreads();
        if (tid < NP) pixels[tid] = g_pix[start + pb + min(tid, npc - 1)];
        __syncthreads();

        // stage slab c=0
#pragma unroll
        for (int i = 0; i < NSTG; i++) {
            if (qv_ok[i]) {
                int pix = pixels[pp[i]];
                int yy = (pix >> 6) + sy[i], xx = (pix & 63) + sx[i];
                float4 v = make_float4(0.f, 0.f, 0.f, 0.f);
                if ((unsigned)yy < 64u && (unsigned)xx < 64u)
                    v = *(const float4*)&g_h[((yy << 6) + xx) * 64 + chq[i]];
                sv[i] = v;
            }
        }

        ull acc0 = 0, acc1 = 0;

        for (int c = 0; c < 4; c++) {
#pragma unroll
            for (int i = 0; i < NSTG; i++) {
                if (qv_ok[i]) {
                    patch[soff[i] + 0 * 9 * PSTRIDE] = sv[i].x;
                    patch[soff[i] + 1 * 9 * PSTRIDE] = sv[i].y;
                    patch[soff[i] + 2 * 9 * PSTRIDE] = sv[i].z;
                    patch[soff[i] + 3 * 9 * PSTRIDE] = sv[i].w;
                }
            }
            __syncthreads();

            if (c < 3) {
                int c0n = (c + 1) * 16;
#pragma unroll
                for (int i = 0; i < NSTG; i++) {
                    if (qv_ok[i]) {
                        int pix = pixels[pp[i]];
                        int yy = (pix >> 6) + sy[i], xx = (pix & 63) + sx[i];
                        float4 v = make_float4(0.f, 0.f, 0.f, 0.f);
                        if ((unsigned)yy < 64u && (unsigned)xx < 64u)
                            v = *(const float4*)&g_h[((yy << 6) + xx) * 64 + c0n + chq[i]];
                        sv[i] = v;
                    }
                }
            }

            if (!waited) {
                unsigned done;
                do {
                    asm volatile("{\n\t.reg .pred p;\n\t"
                                 "mbarrier.try_wait.parity.acquire.cta.shared::cta.b64 p, [%1], 0, 0x989680;\n\t"
                                 "selp.b32 %0, 1, 0, p;\n\t}"
                                 : "=r"(done) : "r"(mb) : "memory");
                } while (!done);
                waited = true;
            }

            // GEMM slab
            {
                const float* Fo = Fs + o * FROW + c * 144;
                const float* Pb = patch + pxg * 4;
#pragma unroll 8
                for (int ck = 0; ck < 144; ck++) {
                    ull d = pack_dup(Fo[ck]);
                    fma2(acc0, d, *(const ull*)&Pb[ck * PSTRIDE]);
                    fma2(acc1, d, *(const ull*)&Pb[ck * PSTRIDE + 2]);
                }
            }
            __syncthreads();
        }

        float a[4];
        unpack2(a[0], a[1], acc0);
        unpack2(a[2], a[3], acc1);
        float bs = Fs[o * FROW + 576];

        // dyn bias + relu -> g_z (HWC; 32 consecutive o per lane group = coalesced)
#pragma unroll
        for (int j = 0; j < 4; j++) {
            int p = pxg * 4 + j;
            if (p < npc) {
                int pix = pixels[p];
                g_z[pix * 64 + half * 32 + o] = fmaxf(a[j] + bs, 0.f);
            }
        }
    }
}

// ---------- launch 4: 1x1 conv + b2 + residual + relu (128 blocks x 32 px) ----------
__global__ __launch_bounds__(256) void k_body2(const float* __restrict__ x,
                                               const float* __restrict__ w2,
                                               const float* __restrict__ b2,
                                               float* __restrict__ out) {
    __shared__ float zs[64 * 33];          // [c][p] transposed, stride 33
    __shared__ __align__(16) float w2t[64 * 68];  // [c][o]
    int tid = threadIdx.x;
    int pixbase = blockIdx.x * 32;

    // stage w2 transposed
    for (int idx = tid; idx < 4096; idx += 256) {
        w2t[(idx & 63) * 68 + (idx >> 6)] = w2[idx];
    }
    // stage z tile transposed: g_z[(pixbase+p)*64 + c]
#pragma unroll
    for (int k = 0; k < 2; k++) {
        int q = tid + k * 256;             // 512 float4 units: p = q>>4, c = (q&15)*4
        int p = q >> 4, c4 = (q & 15) * 4;
        float4 v = *(const float4*)&g_z[(pixbase + p) * 64 + c4];
        zs[(c4 + 0) * 33 + p] = v.x;
        zs[(c4 + 1) * 33 + p] = v.y;
        zs[(c4 + 2) * 33 + p] = v.z;
        zs[(c4 + 3) * 33 + p] = v.w;
    }
    __syncthreads();

    int lane = tid & 31;    // pixel
    int og = tid >> 5;      // 8 oc-groups of 8
    float acc[8];
#pragma unroll
    for (int i = 0; i < 8; i++) acc[i] = __ldg(&b2[og * 8 + i]);

#pragma unroll 4
    for (int c = 0; c < 64; c++) {
        float zv = zs[c * 33 + lane];
        float4 wa = *(const float4*)&w2t[c * 68 + og * 8];
        float4 wb = *(const float4*)&w2t[c * 68 + og * 8 + 4];
        acc[0] += wa.x * zv; acc[1] += wa.y * zv;
        acc[2] += wa.z * zv; acc[3] += wa.w * zv;
        acc[4] += wb.x * zv; acc[5] += wb.y * zv;
        acc[6] += wb.z * zv; acc[7] += wb.w * zv;
    }

#pragma unroll
    for (int i = 0; i < 8; i++) {
        int o = og * 8 + i;
        float v = acc[i] + x[o * HWPIX + pixbase + lane];
        out[o * HWPIX + pixbase + lane] = fmaxf(v, 0.f);
    }
}

extern "C" void kernel_launch(void* const* d_in, const int* in_sizes, int n_in,
                              void* d_out, int out_size) {
    const float* x   = (const float*)d_in[0];
    const int* bk    = (const int*)d_in[1];
    const float* w1  = (const float*)d_in[2];
    const float* b1  = (const float*)d_in[3];
    const float* emb = (const float*)d_in[4];
    const float* w2  = (const float*)d_in[5];
    const float* b2  = (const float*)d_in[6];
    float* out = (float*)d_out;

    k_conv1hist<<<272, 256>>>(x, w1, b1, bk);
    k_scanscatter<<<16, 256>>>(bk);

    size_t smem = (size_t)(HALF_F + 144 * PSTRIDE) * sizeof(float); // 93440 B
    cudaFuncSetAttribute(k_dyn, cudaFuncAttributeMaxDynamicSharedMemorySize, (int)smem);
    k_dyn<<<NT * 2, 256, smem>>>(emb);

    k_body2<<<128, 256>>>(x, w2, b2, out);
}

// round 8
// speedup vs baseline: 1.4136x; 1.0676x over previous
#include <cuda_runtime.h>

#define HWPIX 4096
#define NT 216
#define EMBROW 36928      // 64*577 floats per bucket
#define FROW 577
#define HALF_F 18464      // 32*577 floats
#define HALF_FB 73856     // bytes
#define NP 32
#define PSTRIDE 34
#define NSTG 5

typedef unsigned long long ull;

__device__ __forceinline__ ull pack_dup(float v) {
    ull r;
    asm("mov.b64 %0, {%1, %1};" : "=l"(r) : "f"(v));
    return r;
}
__device__ __forceinline__ void fma2(ull& acc, ull a, ull b) {
    asm("fma.rn.f32x2 %0, %1, %2, %0;" : "+l"(acc) : "l"(a), "l"(b));
}
__device__ __forceinline__ void unpack2(float& lo, float& hi, ull v) {
    asm("mov.b64 {%0, %1}, %2;" : "=f"(lo), "=f"(hi) : "l"(v));
}
__device__ __forceinline__ unsigned smem_u32(const void* p) {
    unsigned a;
    asm("{ .reg .u64 t; cvta.to.shared.u64 t, %1; cvt.u32.u64 %0, t; }" : "=r"(a) : "l"(p));
    return a;
}

// ---------- device scratch ----------
__device__ __align__(16) float g_h[HWPIX * 64];   // conv1 out, HWC
__device__ __align__(16) float g_z[HWPIX * 64];   // dyn-conv out (relu'd), HWC
__device__ int g_hist16[16][NT];
__device__ int g_count[NT];
__device__ int g_start[NT];
__device__ int g_order[NT];
__device__ int g_pix[HWPIX];

// ---------- launch 1: conv1 (256 blocks, oc-split x4) + histogram (16 blocks) ----------
__global__ __launch_bounds__(256) void k_conv1hist(const float* __restrict__ x,
                                                   const float* __restrict__ w1,
                                                   const float* __restrict__ b1,
                                                   const int* __restrict__ buckets) {
    int blk = blockIdx.x;
    int tid = threadIdx.x;

    if (blk >= 256) {
        __shared__ int hist[NT];
        int hb = blk - 256;
        for (int i = tid; i < NT; i += 256) hist[i] = 0;
        __syncthreads();
        atomicAdd(&hist[buckets[hb * 256 + tid]], 1);
        __syncthreads();
        for (int i = tid; i < NT; i += 256) g_hist16[hb][i] = hist[i];
        return;
    }

    int tile = blk >> 2;
    int ocq = blk & 3;
    int g = tile >> 4;
    int y0 = ((tile >> 2) & 3) * 16, x0 = (tile & 3) * 16;

    __shared__ float xs[16][18][18];
    __shared__ __align__(16) float wsm[144 * 4];

    for (int idx = tid; idx < 576; idx += 256) {
        int i = idx / 144, m = idx - i * 144;
        wsm[m * 4 + i] = w1[(g * 16 + ocq * 4 + i) * 144 + m];
    }
    for (int idx = tid; idx < 16 * 324; idx += 256) {
        int ci = idx / 324, r = idx - ci * 324;
        int yl = r / 18, xl = r - yl * 18;
        int yy = y0 - 1 + yl, xx = x0 - 1 + xl;
        float v = 0.f;
        if ((unsigned)yy < 64u && (unsigned)xx < 64u)
            v = x[(g * 16 + ci) * HWPIX + yy * 64 + xx];
        xs[ci][yl][xl] = v;
    }
    __syncthreads();

    int ty = tid >> 4, tx = tid & 15;
    float acc[4];
#pragma unroll
    for (int i = 0; i < 4; i++) acc[i] = __ldg(&b1[g * 16 + ocq * 4 + i]);

    for (int ci = 0; ci < 16; ci++) {
#pragma unroll
        for (int s = 0; s < 9; s++) {
            float xv = xs[ci][ty + s / 3][tx + s % 3];
            float4 w = *(const float4*)&wsm[(ci * 9 + s) * 4];
            acc[0] += w.x * xv;
            acc[1] += w.y * xv;
            acc[2] += w.z * xv;
            acc[3] += w.w * xv;
        }
    }
    int gy = y0 + ty, gx = x0 + tx;
    float4 r;
    r.x = fmaxf(acc[0], 0.f);
    r.y = fmaxf(acc[1], 0.f);
    r.z = fmaxf(acc[2], 0.f);
    r.w = fmaxf(acc[3], 0.f);
    *(float4*)&g_h[(gy * 64 + gx) * 64 + g * 16 + ocq * 4] = r;
}

// ---------- launch 2: fused scan + scatter (16 blocks) ----------
__global__ __launch_bounds__(256) void k_scanscatter(const int* __restrict__ buckets) {
    __shared__ int cnt[256];
    __shared__ int scan[256];
    __shared__ int cur[NT];
    int tid = threadIdx.x;
    int j = blockIdx.x;

    int v = 0;
    if (tid < NT)
#pragma unroll
        for (int k = 0; k < 16; k++) v += g_hist16[k][tid];
    cnt[tid] = v;
    scan[tid] = v;
    __syncthreads();
    for (int off = 1; off < 256; off <<= 1) {
        int t = (tid >= off) ? scan[tid - off] : 0;
        __syncthreads();
        scan[tid] += t;
        __syncthreads();
    }
    if (tid < NT) {
        int excl = scan[tid] - v;
        int off = excl;
        for (int k = 0; k < j; k++) off += g_hist16[k][tid];
        cur[tid] = off;
        if (j == 0) {
            g_count[tid] = v;
            g_start[tid] = excl;
            int rank = 0;
            for (int q = 0; q < NT; q++) {
                int cq = cnt[q];
                rank += (cq > v) || (cq == v && q < tid);
            }
            g_order[rank] = tid;
        }
    }
    __syncthreads();
    int i = j * 256 + tid;
    int b = buckets[i];
    int pos = atomicAdd(&cur[b], 1);
    g_pix[pos] = i;
}

// ---------- launch 3: dynamic conv, 432 blocks (bucket x o-half) ----------
__global__ __launch_bounds__(256) void k_dyn(const float* __restrict__ emb) {
    extern __shared__ float sm[];
    float* Fs = sm;                      // 32 x 577 (TMA target)
    float* patch = sm + HALF_F;          // 144 x 34
    __shared__ int pixels[NP];
    __shared__ __align__(8) ull mbar;

    int t = g_order[blockIdx.x >> 1];
    int half = blockIdx.x & 1;
    int tid = threadIdx.x;
    int n = g_count[t];
    int start = g_start[t];
    if (n == 0) return;

    unsigned mb = smem_u32(&mbar);
    if (tid == 0) {
        asm volatile("mbarrier.init.shared.b64 [%0], 1;" :: "r"(mb) : "memory");
        asm volatile("fence.proxy.async.shared::cta;" ::: "memory");
        asm volatile("mbarrier.arrive.expect_tx.shared.b64 _, [%0], %1;"
                     :: "r"(mb), "r"(HALF_FB) : "memory");
        asm volatile("cp.async.bulk.shared::cta.global.mbarrier::complete_tx::bytes "
                     "[%0], [%1], %2, [%3];"
                     :: "r"(smem_u32(Fs)),
                        "l"(emb + (size_t)t * EMBROW + half * HALF_F),
                        "r"(HALF_FB), "r"(mb) : "memory");
    }

    int o = tid & 31;        // lane: o within half (577 % 32 == 1 -> conflict-free)
    int pxg = tid >> 5;      // warp id: pixels 4pxg .. 4pxg+3

    int pp[NSTG], soff[NSTG], sy[NSTG], sx[NSTG], chq[NSTG];
    bool qv_ok[NSTG];
#pragma unroll
    for (int i = 0; i < NSTG; i++) {
        int q = tid + i * 256;
        qv_ok[i] = (q < 1152);
        int qq = qv_ok[i] ? q : 0;
        int p = qq / 36;
        int r = qq - p * 36;
        int cq = r & 3, s = r >> 2;
        pp[i] = p;
        sy[i] = s / 3 - 1;
        sx[i] = s % 3 - 1;
        soff[i] = ((cq * 4) * 9 + s) * PSTRIDE + p;
        chq[i] = cq * 4;
    }

    float4 sv[NSTG];
    bool waited = false;

    for (int pb = 0; pb < n; pb += NP) {
        int npc = min(NP, n - pb);
        bool live = (pxg * 4 < npc);     // warp computes real pixels?
        __syncthreads();
        if (tid < NP) pixels[tid] = g_pix[start + pb + min(tid, npc - 1)];
        __syncthreads();

        // stage slab c=0
#pragma unroll
        for (int i = 0; i < NSTG; i++) {
            if (qv_ok[i]) {
                int pix = pixels[pp[i]];
                int yy = (pix >> 6) + sy[i], xx = (pix & 63) + sx[i];
                float4 v = make_float4(0.f, 0.f, 0.f, 0.f);
                if ((unsigned)yy < 64u && (unsigned)xx < 64u)
                    v = *(const float4*)&g_h[((yy << 6) + xx) * 64 + chq[i]];
                sv[i] = v;
            }
        }

        ull acc0 = 0, acc1 = 0;

        for (int c = 0; c < 4; c++) {
#pragma unroll
            for (int i = 0; i < NSTG; i++) {
                if (qv_ok[i]) {
                    patch[soff[i] + 0 * 9 * PSTRIDE] = sv[i].x;
                    patch[soff[i] + 1 * 9 * PSTRIDE] = sv[i].y;
                    patch[soff[i] + 2 * 9 * PSTRIDE] = sv[i].z;
                    patch[soff[i] + 3 * 9 * PSTRIDE] = sv[i].w;
                }
            }
            __syncthreads();

            if (c < 3) {
                int c0n = (c + 1) * 16;
#pragma unroll
                for (int i = 0; i < NSTG; i++) {
                    if (qv_ok[i]) {
                        int pix = pixels[pp[i]];
                        int yy = (pix >> 6) + sy[i], xx = (pix & 63) + sx[i];
                        float4 v = make_float4(0.f, 0.f, 0.f, 0.f);
                        if ((unsigned)yy < 64u && (unsigned)xx < 64u)
                            v = *(const float4*)&g_h[((yy << 6) + xx) * 64 + c0n + chq[i]];
                        sv[i] = v;
                    }
                }
            }

            if (!waited) {
                unsigned done;
                do {
                    asm volatile("{\n\t.reg .pred p;\n\t"
                                 "mbarrier.try_wait.parity.acquire.cta.shared::cta.b64 p, [%1], 0, 0x989680;\n\t"
                                 "selp.b32 %0, 1, 0, p;\n\t}"
                                 : "=r"(done) : "r"(mb) : "memory");
                } while (!done);
                waited = true;
            }

            // GEMM slab — skipped entirely by padded warps
            if (live) {
                const float* Fo = Fs + o * FROW + c * 144;
                const float* Pb = patch + pxg * 4;
#pragma unroll 8
                for (int ck = 0; ck < 144; ck++) {
                    ull d = pack_dup(Fo[ck]);
                    fma2(acc0, d, *(const ull*)&Pb[ck * PSTRIDE]);
                    fma2(acc1, d, *(const ull*)&Pb[ck * PSTRIDE + 2]);
                }
            }
            __syncthreads();
        }

        if (live) {
            float a[4];
            unpack2(a[0], a[1], acc0);
            unpack2(a[2], a[3], acc1);
            float bs = Fs[o * FROW + 576];
#pragma unroll
            for (int j = 0; j < 4; j++) {
                int p = pxg * 4 + j;
                if (p < npc) {
                    int pix = pixels[p];
                    g_z[pix * 64 + half * 32 + o] = fmaxf(a[j] + bs, 0.f);
                }
            }
        }
    }
}

// ---------- launch 4: 1x1 conv + b2 + residual + relu (256 blocks x 16 px) ----------
__global__ __launch_bounds__(256) void k_body2(const float* __restrict__ x,
                                               const float* __restrict__ w2,
                                               const float* __restrict__ b2,
                                               float* __restrict__ out) {
    __shared__ float zs[64 * 17];                 // [c][p], stride 17
    __shared__ __align__(16) float w2t[64 * 68];  // [c][o]
    int tid = threadIdx.x;
    int pixbase = blockIdx.x * 16;

    // stage w2 transposed
    for (int idx = tid; idx < 4096; idx += 256) {
        w2t[(idx & 63) * 68 + (idx >> 6)] = w2[idx];
    }
    // stage z tile transposed: 16 px x 64 c = 256 float4 units
    {
        int p = tid >> 4, c4 = (tid & 15) * 4;
        float4 v = *(const float4*)&g_z[(pixbase + p) * 64 + c4];
        zs[(c4 + 0) * 17 + p] = v.x;
        zs[(c4 + 1) * 17 + p] = v.y;
        zs[(c4 + 2) * 17 + p] = v.z;
        zs[(c4 + 3) * 17 + p] = v.w;
    }
    __syncthreads();

    int px = tid & 15;
    int og = tid >> 4;      // 16 groups of 4 o
    float acc[4];
#pragma unroll
    for (int i = 0; i < 4; i++) acc[i] = __ldg(&b2[og * 4 + i]);

#pragma unroll 8
    for (int c = 0; c < 64; c++) {
        float zv = zs[c * 17 + px];
        float4 w = *(const float4*)&w2t[c * 68 + og * 4];
        acc[0] += w.x * zv;
        acc[1] += w.y * zv;
        acc[2] += w.z * zv;
        acc[3] += w.w * zv;
    }

#pragma unroll
    for (int i = 0; i < 4; i++) {
        int o = og * 4 + i;
        float v = acc[i] + x[o * HWPIX + pixbase + px];
        out[o * HWPIX + pixbase + px] = fmaxf(v, 0.f);
    }
}

extern "C" void kernel_launch(void* const* d_in, const int* in_sizes, int n_in,
                              void* d_out, int out_size) {
    const float* x   = (const float*)d_in[0];
    const int* bk    = (const int*)d_in[1];
    const float* w1  = (const float*)d_in[2];
    const float* b1  = (const float*)d_in[3];
    const float* emb = (const float*)d_in[4];
    const float* w2  = (const float*)d_in[5];
    const float* b2  = (const float*)d_in[6];
    float* out = (float*)d_out;

    k_conv1hist<<<272, 256>>>(x, w1, b1, bk);
    k_scanscatter<<<16, 256>>>(bk);

    size_t smem = (size_t)(HALF_F + 144 * PSTRIDE) * sizeof(float); // 93440 B
    cudaFuncSetAttribute(k_dyn, cudaFuncAttributeMaxDynamicSharedMemorySize, (int)smem);
    k_dyn<<<NT * 2, 256, smem>>>(emb);

    k_body2<<<256, 256>>>(x, w2, b2, out);
}

// round 10
// speedup vs baseline: 1.4895x; 1.0537x over previous
#include <cuda_runtime.h>

#define HWPIX 4096
#define NT 216
#define EMBROW 36928      // 64*577 floats per bucket
#define FROW 577
#define HALF_F 18464      // 32*577 floats
#define HALF_FB 73856     // bytes
#define NP 32
#define PSTRIDE 34
#define NSTG 5

typedef unsigned long long ull;

__device__ __forceinline__ ull pack_dup(float v) {
    ull r;
    asm("mov.b64 %0, {%1, %1};" : "=l"(r) : "f"(v));
    return r;
}
__device__ __forceinline__ void fma2(ull& acc, ull a, ull b) {
    asm("fma.rn.f32x2 %0, %1, %2, %0;" : "+l"(acc) : "l"(a), "l"(b));
}
__device__ __forceinline__ void unpack2(float& lo, float& hi, ull v) {
    asm("mov.b64 {%0, %1}, %2;" : "=f"(lo), "=f"(hi) : "l"(v));
}
__device__ __forceinline__ unsigned smem_u32(const void* p) {
    unsigned a;
    asm("{ .reg .u64 t; cvta.to.shared.u64 t, %1; cvt.u32.u64 %0, t; }" : "=r"(a) : "l"(p));
    return a;
}

// ---------- device scratch ----------
__device__ __align__(16) float g_h[HWPIX * 64];   // conv1 out, HWC
__device__ __align__(16) float g_z[HWPIX * 64];   // dyn-conv out (relu'd), HWC
__device__ int g_hist16[16][NT];
__device__ int g_count[NT];
__device__ int g_start[NT];
__device__ int g_order[NT];
__device__ int g_pix[HWPIX];

// ---------- launch 1: conv1 (256 blocks, oc-split x4) + histogram (16 blocks) ----------
__global__ __launch_bounds__(256) void k_conv1hist(const float* __restrict__ x,
                                                   const float* __restrict__ w1,
                                                   const float* __restrict__ b1,
                                                   const int* __restrict__ buckets) {
    int blk = blockIdx.x;
    int tid = threadIdx.x;

    if (blk >= 256) {
        __shared__ int hist[NT];
        int hb = blk - 256;
        for (int i = tid; i < NT; i += 256) hist[i] = 0;
        __syncthreads();
        atomicAdd(&hist[buckets[hb * 256 + tid]], 1);
        __syncthreads();
        for (int i = tid; i < NT; i += 256) g_hist16[hb][i] = hist[i];
        return;
    }

    int tile = blk >> 2;
    int ocq = blk & 3;
    int g = tile >> 4;
    int y0 = ((tile >> 2) & 3) * 16, x0 = (tile & 3) * 16;

    __shared__ float xs[16][18][18];
    __shared__ __align__(16) float wsm[144 * 4];

    for (int idx = tid; idx < 576; idx += 256) {
        int i = idx / 144, m = idx - i * 144;
        wsm[m * 4 + i] = w1[(g * 16 + ocq * 4 + i) * 144 + m];
    }
    for (int idx = tid; idx < 16 * 324; idx += 256) {
        int ci = idx / 324, r = idx - ci * 324;
        int yl = r / 18, xl = r - yl * 18;
        int yy = y0 - 1 + yl, xx = x0 - 1 + xl;
        float v = 0.f;
        if ((unsigned)yy < 64u && (unsigned)xx < 64u)
            v = x[(g * 16 + ci) * HWPIX + yy * 64 + xx];
        xs[ci][yl][xl] = v;
    }
    __syncthreads();

    int ty = tid >> 4, tx = tid & 15;
    float acc[4];
#pragma unroll
    for (int i = 0; i < 4; i++) acc[i] = __ldg(&b1[g * 16 + ocq * 4 + i]);

    for (int ci = 0; ci < 16; ci++) {
#pragma unroll
        for (int s = 0; s < 9; s++) {
            float xv = xs[ci][ty + s / 3][tx + s % 3];
            float4 w = *(const float4*)&wsm[(ci * 9 + s) * 4];
            acc[0] += w.x * xv;
            acc[1] += w.y * xv;
            acc[2] += w.z * xv;
            acc[3] += w.w * xv;
        }
    }
    int gy = y0 + ty, gx = x0 + tx;
    float4 r;
    r.x = fmaxf(acc[0], 0.f);
    r.y = fmaxf(acc[1], 0.f);
    r.z = fmaxf(acc[2], 0.f);
    r.w = fmaxf(acc[3], 0.f);
    *(float4*)&g_h[(gy * 64 + gx) * 64 + g * 16 + ocq * 4] = r;
}

// ---------- launch 2: fused scan + scatter (16 blocks) ----------
__global__ __launch_bounds__(256) void k_scanscatter(const int* __restrict__ buckets) {
    __shared__ int cnt[256];
    __shared__ int scan[256];
    __shared__ int cur[NT];
    int tid = threadIdx.x;
    int j = blockIdx.x;

    int v = 0;
    if (tid < NT)
#pragma unroll
        for (int k = 0; k < 16; k++) v += g_hist16[k][tid];
    cnt[tid] = v;
    scan[tid] = v;
    __syncthreads();
    for (int off = 1; off < 256; off <<= 1) {
        int t = (tid >= off) ? scan[tid - off] : 0;
        __syncthreads();
        scan[tid] += t;
        __syncthreads();
    }
    if (tid < NT) {
        int excl = scan[tid] - v;
        int off = excl;
        for (int k = 0; k < j; k++) off += g_hist16[k][tid];
        cur[tid] = off;
        if (j == 0) {
            g_count[tid] = v;
            g_start[tid] = excl;
            int rank = 0;
            for (int q = 0; q < NT; q++) {
                int cq = cnt[q];
                rank += (cq > v) || (cq == v && q < tid);
            }
            g_order[rank] = tid;
        }
    }
    __syncthreads();
    int i = j * 256 + tid;
    int b = buckets[i];
    int pos = atomicAdd(&cur[b], 1);
    g_pix[pos] = i;
}

// ---------- launch 3: dynamic conv, 432 blocks (bucket x o-half) ----------
__global__ __launch_bounds__(256) void k_dyn(const float* __restrict__ emb) {
    extern __shared__ float sm[];
    float* Fs = sm;                      // 32 x 577 (TMA target)
    float* patch = sm + HALF_F;          // 144 x 34
    __shared__ int pixels[NP];
    __shared__ __align__(8) ull mbar;

    int t = g_order[blockIdx.x >> 1];
    int half = blockIdx.x & 1;
    int tid = threadIdx.x;
    int n = g_count[t];
    int start = g_start[t];
    if (n == 0) return;

    unsigned mb = smem_u32(&mbar);
    if (tid == 0) {
        asm volatile("mbarrier.init.shared.b64 [%0], 1;" :: "r"(mb) : "memory");
        asm volatile("fence.proxy.async.shared::cta;" ::: "memory");
        asm volatile("mbarrier.arrive.expect_tx.shared.b64 _, [%0], %1;"
                     :: "r"(mb), "r"(HALF_FB) : "memory");
        asm volatile("cp.async.bulk.shared::cta.global.mbarrier::complete_tx::bytes "
                     "[%0], [%1], %2, [%3];"
                     :: "r"(smem_u32(Fs)),
                        "l"(emb + (size_t)t * EMBROW + half * HALF_F),
                        "r"(HALF_FB), "r"(mb) : "memory");
    }

    int o = tid & 31;        // lane: o within half (577 % 32 == 1 -> conflict-free)
    int pxg = tid >> 5;      // warp id: pixels 4pxg .. 4pxg+3

    int pp[NSTG], soff[NSTG], sy[NSTG], sx[NSTG], chq[NSTG];
    bool qv_ok[NSTG];
#pragma unroll
    for (int i = 0; i < NSTG; i++) {
        int q = tid + i * 256;
        qv_ok[i] = (q < 1152);
        int qq = qv_ok[i] ? q : 0;
        int p = qq / 36;
        int r = qq - p * 36;
        int cq = r & 3, s = r >> 2;
        pp[i] = p;
        sy[i] = s / 3 - 1;
        sx[i] = s % 3 - 1;
        soff[i] = ((cq * 4) * 9 + s) * PSTRIDE + p;
        chq[i] = cq * 4;
    }

    float4 sv[NSTG];
    bool waited = false;

    for (int pb = 0; pb < n; pb += NP) {
        int npc = min(NP, n - pb);
        bool live = (pxg * 4 < npc);
        __syncthreads();
        if (tid < NP) pixels[tid] = g_pix[start + pb + min(tid, npc - 1)];
        __syncthreads();

        // stage slab c=0
#pragma unroll
        for (int i = 0; i < NSTG; i++) {
            if (qv_ok[i]) {
                int pix = pixels[pp[i]];
                int yy = (pix >> 6) + sy[i], xx = (pix & 63) + sx[i];
                float4 v = make_float4(0.f, 0.f, 0.f, 0.f);
                if ((unsigned)yy < 64u && (unsigned)xx < 64u)
                    v = *(const float4*)&g_h[((yy << 6) + xx) * 64 + chq[i]];
                sv[i] = v;
            }
        }

        ull acc0 = 0, acc1 = 0;

        for (int c = 0; c < 4; c++) {
#pragma unroll
            for (int i = 0; i < NSTG; i++) {
                if (qv_ok[i]) {
                    patch[soff[i] + 0 * 9 * PSTRIDE] = sv[i].x;
                    patch[soff[i] + 1 * 9 * PSTRIDE] = sv[i].y;
                    patch[soff[i] + 2 * 9 * PSTRIDE] = sv[i].z;
                    patch[soff[i] + 3 * 9 * PSTRIDE] = sv[i].w;
                }
            }
            __syncthreads();

            if (c < 3) {
                int c0n = (c + 1) * 16;
#pragma unroll
                for (int i = 0; i < NSTG; i++) {
                    if (qv_ok[i]) {
                        int pix = pixels[pp[i]];
                        int yy = (pix >> 6) + sy[i], xx = (pix & 63) + sx[i];
                        float4 v = make_float4(0.f, 0.f, 0.f, 0.f);
                        if ((unsigned)yy < 64u && (unsigned)xx < 64u)
                            v = *(const float4*)&g_h[((yy << 6) + xx) * 64 + c0n + chq[i]];
                        sv[i] = v;
                    }
                }
            }

            if (!waited) {
                unsigned done;
                do {
                    asm volatile("{\n\t.reg .pred p;\n\t"
                                 "mbarrier.try_wait.parity.acquire.cta.shared::cta.b64 p, [%1], 0, 0x989680;\n\t"
                                 "selp.b32 %0, 1, 0, p;\n\t}"
                                 : "=r"(done) : "r"(mb) : "memory");
                } while (!done);
                waited = true;
            }

            if (live) {
                const float* Fo = Fs + o * FROW + c * 144;
                const float* Pb = patch + pxg * 4;
#pragma unroll 8
                for (int ck = 0; ck < 144; ck++) {
                    ull d = pack_dup(Fo[ck]);
                    fma2(acc0, d, *(const ull*)&Pb[ck * PSTRIDE]);
                    fma2(acc1, d, *(const ull*)&Pb[ck * PSTRIDE + 2]);
                }
            }
            __syncthreads();
        }

        if (live) {
            float a[4];
            unpack2(a[0], a[1], acc0);
            unpack2(a[2], a[3], acc1);
            float bs = Fs[o * FROW + 576];
#pragma unroll
            for (int j = 0; j < 4; j++) {
                int p = pxg * 4 + j;
                if (p < npc) {
                    int pix = pixels[p];
                    g_z[pix * 64 + half * 32 + o] = fmaxf(a[j] + bs, 0.f);
                }
            }
        }
    }
}

// ---------- launch 4: 1x1 conv + b2 + residual + relu (256 blocks x 16 px) ----------
// Transpose-free: z staged [px][c], w2 staged linear [o][c], c vectorized by 4.
__global__ __launch_bounds__(256) void k_body2(const float* __restrict__ x,
                                               const float* __restrict__ w2,
                                               const float* __restrict__ b2,
                                               float* __restrict__ out) {
    __shared__ __align__(16) float zs[16][68];    // [p][c], row pad 68
    __shared__ __align__(16) float w2s[4096];     // [o][c] linear
    int tid = threadIdx.x;
    int pixbase = blockIdx.x * 16;

    // stage w2 linear: 1024 float4 / 256 threads = 4 each, coalesced, conflict-free
#pragma unroll
    for (int k = 0; k < 4; k++) {
        int idx = (tid + k * 256) * 4;
        *(float4*)&w2s[idx] = *(const float4*)(w2 + idx);
    }
    // stage z: 16 px x 16 float4 = 256 units, one per thread, direct copy
    {
        int p = tid >> 4, c4 = (tid & 15) * 4;
        *(float4*)&zs[p][c4] = *(const float4*)&g_z[(pixbase + p) * 64 + c4];
    }

    int px = tid & 15;
    int og = tid >> 4;      // 16 groups of 4 o

    // prefetch residual (overlaps staging latency)
    float resid[4];
#pragma unroll
    for (int i = 0; i < 4; i++) resid[i] = x[(og * 4 + i) * HWPIX + pixbase + px];

    float acc[4];
#pragma unroll
    for (int i = 0; i < 4; i++) acc[i] = __ldg(&b2[og * 4 + i]);

    __syncthreads();

#pragma unroll
    for (int c4 = 0; c4 < 64; c4 += 4) {
        float4 z = *(const float4*)&zs[px][c4];
#pragma unroll
        for (int i = 0; i < 4; i++) {
            float4 w = *(const float4*)&w2s[(og * 4 + i) * 64 + c4];
            acc[i] += w.x * z.x;
            acc[i] += w.y * z.y;
            acc[i] += w.z * z.z;
            acc[i] += w.w * z.w;
        }
    }

#pragma unroll
    for (int i = 0; i < 4; i++) {
        int o = og * 4 + i;
        out[o * HWPIX + pixbase + px] = fmaxf(acc[i] + resid[i], 0.f);
    }
}

extern "C" void kernel_launch(void* const* d_in, const int* in_sizes, int n_in,
                              void* d_out, int out_size) {
    const float* x   = (const float*)d_in[0];
    const int* bk    = (const int*)d_in[1];
    const float* w1  = (const float*)d_in[2];
    const float* b1  = (const float*)d_in[3];
    const float* emb = (const float*)d_in[4];
    const float* w2  = (const float*)d_in[5];
    const float* b2  = (const float*)d_in[6];
    float* out = (float*)d_out;

    k_conv1hist<<<272, 256>>>(x, w1, b1, bk);
    k_scanscatter<<<16, 256>>>(bk);

    size_t smem = (size_t)(HALF_F + 144 * PSTRIDE) * sizeof(float); // 93440 B
    cudaFuncSetAttribute(k_dyn, cudaFuncAttributeMaxDynamicSharedMemorySize, (int)smem);
    k_dyn<<<NT * 2, 256, smem>>>(emb);

    k_body2<<<256, 256>>>(x, w2, b2, out);
}